// round 1
// baseline (speedup 1.0000x reference)
#include <cuda_runtime.h>

#define NATOMS 512
#define BATCH  32
#define NN     (NATOMS * NATOMS)
#define INV2PI 0.15915494309189535f

struct F3 { float x, y, z; };

__device__ __forceinline__ F3 f3sub(F3 a, F3 b) { return {a.x - b.x, a.y - b.y, a.z - b.z}; }
__device__ __forceinline__ F3 f3cross(F3 a, F3 b) {
    return {a.y * b.z - a.z * b.y,
            a.z * b.x - a.x * b.z,
            a.x * b.y - a.y * b.x};
}
__device__ __forceinline__ float f3dot(F3 a, F3 b) { return a.x * b.x + a.y * b.y + a.z * b.z; }

__global__ void zero_kernel(float4* __restrict__ out, int n4) {
    int i = blockIdx.x * blockDim.x + threadIdx.x;
    if (i < n4) out[i] = make_float4(0.f, 0.f, 0.f, 0.f);
}

__global__ __launch_bounds__(256) void writhe_kernel(
    const float* __restrict__ x,
    const int4*  __restrict__ seg,
    float*       __restrict__ out,
    int S)
{
    __shared__ float sx[NATOMS * 3];

    const int b = blockIdx.y;
    const float* xb = x + (size_t)b * (NATOMS * 3);

    // Stage this batch's coordinates (6 KB) into shared memory.
    #pragma unroll
    for (int t = threadIdx.x; t < NATOMS * 3; t += 256)
        sx[t] = xb[t];
    __syncthreads();

    const int s = blockIdx.x * 256 + threadIdx.x;
    if (s >= S) return;

    const int4 q = seg[s];   // (i, i+1, j, j+1)

    F3 p0 = {sx[3 * q.x], sx[3 * q.x + 1], sx[3 * q.x + 2]};
    F3 p1 = {sx[3 * q.y], sx[3 * q.y + 1], sx[3 * q.y + 2]};
    F3 p2 = {sx[3 * q.z], sx[3 * q.z + 1], sx[3 * q.z + 2]};
    F3 p3 = {sx[3 * q.w], sx[3 * q.w + 1], sx[3 * q.w + 2]};

    // Displacements (normalization elided: it cancels in the normalized-cross dots
    // and in the sign term).
    F3 e0 = f3sub(p2, p0);
    F3 e1 = f3sub(p3, p0);
    F3 e2 = f3sub(p2, p1);
    F3 e3 = f3sub(p3, p1);

    F3 u0 = f3cross(e0, e1);
    F3 u1 = f3cross(e1, e3);
    F3 u2 = f3cross(e3, e2);
    F3 u3 = f3cross(e2, e0);

    float r0 = rsqrtf(f3dot(u0, u0));
    float r1 = rsqrtf(f3dot(u1, u1));
    float r2 = rsqrtf(f3dot(u2, u2));
    float r3 = rsqrtf(f3dot(u3, u3));

    float t01 = fminf(fmaxf(f3dot(u0, u1) * (r0 * r1), -1.f), 1.f);
    float t12 = fminf(fmaxf(f3dot(u1, u2) * (r1 * r2), -1.f), 1.f);
    float t23 = fminf(fmaxf(f3dot(u2, u3) * (r2 * r3), -1.f), 1.f);
    float t30 = fminf(fmaxf(f3dot(u3, u0) * (r3 * r0), -1.f), 1.f);

    float omega = asinf(t01) + asinf(t12) + asinf(t23) + asinf(t30);

    // sign( (p3-p2) x (p1-p0) . (p2-p0) ) -- scale invariant, so unnormalized.
    float sv  = f3dot(f3cross(f3sub(p3, p2), f3sub(p1, p0)), e0);
    float sgn = (sv > 0.f) ? 1.f : ((sv < 0.f) ? -1.f : 0.f);

    float wr = omega * sgn * INV2PI;

    // Final state of the two sequential JAX scatters + symmetrization:
    //   every segment owns cell (i+1, j+1) (second scatter overwrites first),
    //   and i==0 segments additionally keep their first-scatter cell (0, j).
    float* ob = out + (size_t)b * NN;
    ob[q.y * NATOMS + q.w] = wr;
    ob[q.w * NATOMS + q.y] = wr;
    if (q.x == 0) {
        ob[q.z]          = wr;   // row 0, col j
        ob[q.z * NATOMS] = wr;   // row j, col 0
    }
}

extern "C" void kernel_launch(void* const* d_in, const int* in_sizes, int n_in,
                              void* d_out, int out_size)
{
    // Identify inputs by element count for robustness:
    // x has exactly 32*512*3 = 49152 elements; segments has S*4.
    int xi = (in_sizes[0] == BATCH * NATOMS * 3) ? 0 : 1;
    int si = 1 - xi;

    const float* x   = (const float*)d_in[xi];
    const int4*  seg = (const int4*)d_in[si];
    float*       out = (float*)d_out;
    const int S = in_sizes[si] / 4;

    // 1) Zero the output (it is poisoned before timing).
    int n4 = out_size / 4;                 // out_size = 32*512*512 floats
    zero_kernel<<<(n4 + 255) / 256, 256>>>((float4*)out, n4);

    // 2) Compute writhe per (batch, segment) and scatter.
    dim3 grid((S + 255) / 256, BATCH);
    writhe_kernel<<<grid, 256>>>(x, seg, out, S);
}

// round 2
// speedup vs baseline: 1.2515x; 1.2515x over previous
#include <cuda_runtime.h>

#define NATOMS 512
#define BATCH  32
#define NN     (NATOMS * NATOMS)
#define INV2PI 0.15915494309189535f

struct F3 { float x, y, z; };

__device__ __forceinline__ F3 f3sub(float4 a, float4 b) { return {a.x - b.x, a.y - b.y, a.z - b.z}; }
__device__ __forceinline__ F3 f3cross(F3 a, F3 b) {
    return {a.y * b.z - a.z * b.y,
            a.z * b.x - a.x * b.z,
            a.x * b.y - a.y * b.x};
}
__device__ __forceinline__ float f3dot(F3 a, F3 b) { return a.x * b.x + a.y * b.y + a.z * b.z; }

__device__ __forceinline__ float rsqrt_a(float x) {
    float r; asm("rsqrt.approx.f32 %0, %1;" : "=f"(r) : "f"(x)); return r;
}
__device__ __forceinline__ float sqrt_a(float x) {
    float r; asm("sqrt.approx.f32 %0, %1;" : "=f"(r) : "f"(x)); return r;
}

// Abramowitz & Stegun 4.4.46: asin(t) = pi/2 - sqrt(1-t)*P7(t), 0<=t<=1, |err|<=2e-8.
__device__ __forceinline__ float asin_fast(float x) {
    float t = fminf(fabsf(x), 1.0f);
    float p = fmaf(t, -0.0012624911f, 0.0066700901f);
    p = fmaf(p, t, -0.0170881256f);
    p = fmaf(p, t,  0.0308918810f);
    p = fmaf(p, t, -0.0501743046f);
    p = fmaf(p, t,  0.0889789874f);
    p = fmaf(p, t, -0.2145988016f);
    p = fmaf(p, t,  1.5707963050f);
    float r = 1.5707963267948966f - sqrt_a(1.0f - t) * p;
    return copysignf(r, x);
}

// Zero exactly the cells the scatter never writes:
// the 3 central diagonals |r-c|<=1, plus (0,511) and (511,0). All other cells
// (r,c) with |r-c|>=2 are written by segment (min-1, max-1) or the i=0
// first-scatter row/col. One block per batch.
__global__ void band_zero_kernel(float* __restrict__ out) {
    float* ob = out + (size_t)blockIdx.x * NN;
    int d = threadIdx.x;                 // 0..511
    ob[d * 513] = 0.f;                   // (d, d)
    if (d < NATOMS - 1) {
        ob[d * 513 + 1]   = 0.f;         // (d, d+1)
        ob[d * 513 + 512] = 0.f;         // (d+1, d)
    }
    if (d == 0) {
        ob[NATOMS - 1]            = 0.f; // (0, 511)
        ob[(NATOMS - 1) * NATOMS] = 0.f; // (511, 0)
    }
}

__global__ __launch_bounds__(256) void writhe_kernel(
    const float* __restrict__ x,
    const int4*  __restrict__ seg,
    float*       __restrict__ out,
    int S)
{
    __shared__ float4 sx[NATOMS];

    const int b = blockIdx.y;
    const float* xb = x + (size_t)b * (NATOMS * 3);

    #pragma unroll
    for (int a = threadIdx.x; a < NATOMS; a += 256)
        sx[a] = make_float4(xb[3 * a], xb[3 * a + 1], xb[3 * a + 2], 0.f);
    __syncthreads();

    const int s = blockIdx.x * 256 + threadIdx.x;
    if (s >= S) return;

    const int4 q = __ldg(&seg[s]);   // (i, i+1, j, j+1)

    float4 P0 = sx[q.x];
    float4 P1 = sx[q.y];
    float4 P2 = sx[q.z];
    float4 P3 = sx[q.w];

    // Displacements (normalization elided: cancels in the normalized-cross dots).
    F3 e0 = f3sub(P2, P0);
    F3 e1 = f3sub(P3, P0);
    F3 e2 = f3sub(P2, P1);
    F3 e3 = f3sub(P3, P1);

    F3 u0 = f3cross(e0, e1);
    F3 u1 = f3cross(e1, e3);
    F3 u2 = f3cross(e3, e2);
    F3 u3 = f3cross(e2, e0);

    float r0 = rsqrt_a(f3dot(u0, u0));
    float r1 = rsqrt_a(f3dot(u1, u1));
    float r2 = rsqrt_a(f3dot(u2, u2));
    float r3 = rsqrt_a(f3dot(u3, u3));

    float t01 = f3dot(u0, u1) * (r0 * r1);
    float t12 = f3dot(u1, u2) * (r1 * r2);
    float t23 = f3dot(u2, u3) * (r2 * r3);
    float t30 = f3dot(u3, u0) * (r3 * r0);

    float omega = asin_fast(t01) + asin_fast(t12) + asin_fast(t23) + asin_fast(t30);

    // sign(((p3-p2) x (p1-p0)) . (p2-p0)) == sign(-(u0 . e2))  [triple-product identity]
    float sv  = -f3dot(u0, e2);
    float sgn = (sv > 0.f) ? 1.f : ((sv < 0.f) ? -1.f : 0.f);

    float wr = omega * sgn * INV2PI;

    // Final state of the two sequential JAX scatters + symmetrization:
    // every segment owns (i+1, j+1); i==0 segments additionally keep (0, j).
    float* ob = out + (size_t)b * NN;
    ob[q.y * NATOMS + q.w] = wr;
    ob[q.w * NATOMS + q.y] = wr;
    if (q.x == 0) {
        ob[q.z]          = wr;
        ob[q.z * NATOMS] = wr;
    }
}

extern "C" void kernel_launch(void* const* d_in, const int* in_sizes, int n_in,
                              void* d_out, int out_size)
{
    int xi = (in_sizes[0] == BATCH * NATOMS * 3) ? 0 : 1;
    int si = 1 - xi;

    const float* x   = (const float*)d_in[xi];
    const int4*  seg = (const int4*)d_in[si];
    float*       out = (float*)d_out;
    const int S = in_sizes[si] / 4;

    // 1) Zero only the never-written band cells (output is poisoned before timing).
    band_zero_kernel<<<BATCH, NATOMS>>>(out);

    // 2) Compute writhe per (batch, segment) and scatter.
    dim3 grid((S + 255) / 256, BATCH);
    writhe_kernel<<<grid, 256>>>(x, seg, out, S);
}

// round 3
// speedup vs baseline: 1.7911x; 1.4312x over previous
#include <cuda_runtime.h>

#define NATOMS 512
#define BATCH  32
#define NN     (NATOMS * NATOMS)
#define INV2PI 0.15915494309189535f
#define NT     16            // 512/32 tiles per axis
#define NTILES (NT * (NT + 1) / 2)   // 136

struct F3 { float x, y, z; };

__device__ __forceinline__ F3 f3sub(float4 a, float4 b) { return {a.x - b.x, a.y - b.y, a.z - b.z}; }
__device__ __forceinline__ F3 f3cross(F3 a, F3 b) {
    return {a.y * b.z - a.z * b.y,
            a.z * b.x - a.x * b.z,
            a.x * b.y - a.y * b.x};
}
__device__ __forceinline__ float f3dot(F3 a, F3 b) { return a.x * b.x + a.y * b.y + a.z * b.z; }

__device__ __forceinline__ float rsqrt_a(float x) {
    float r; asm("rsqrt.approx.f32 %0, %1;" : "=f"(r) : "f"(x)); return r;
}
__device__ __forceinline__ float sqrt_a(float x) {
    float r; asm("sqrt.approx.f32 %0, %1;" : "=f"(r) : "f"(x)); return r;
}

// Abramowitz & Stegun 4.4.46: asin(t) = pi/2 - sqrt(1-t)*P7(t), 0<=t<=1, |err|<=2e-8.
__device__ __forceinline__ float asin_fast(float x) {
    float t = fminf(fabsf(x), 1.0f);
    float p = fmaf(t, -0.0012624911f, 0.0066700901f);
    p = fmaf(p, t, -0.0170881256f);
    p = fmaf(p, t,  0.0308918810f);
    p = fmaf(p, t, -0.0501743046f);
    p = fmaf(p, t,  0.0889789874f);
    p = fmaf(p, t, -0.2145988016f);
    p = fmaf(p, t,  1.5707963050f);
    float r = 1.5707963267948966f - sqrt_a(1.0f - t) * p;
    return copysignf(r, x);
}

// Segment set is exactly {(i,j): 0<=i<=509, i+2<=j<=510}, seg row = (i,i+1,j,j+1).
// Final scatter state: every (i,j) owns out[i+1][j+1] (+mirror); i==0 segments
// additionally keep out[0][j] (+mirror). Never-written cells: |r-c|<=1 band,
// (0,511) and (511,0) — zeroed by the diagonal tiles.
__global__ __launch_bounds__(256) void writhe_tile_kernel(
    const float* __restrict__ x,
    float*       __restrict__ out)
{
    __shared__ float4 si[33];
    __shared__ float4 sj4[33];
    __shared__ float  smwr[32][33];

    // Decode upper-triangular tile index.
    int k = blockIdx.x, ti = 0;
    while (k >= NT - ti) { k -= NT - ti; ti++; }
    const int tj = ti + k;
    const int i0 = ti * 32, j0 = tj * 32;

    const int b = blockIdx.y;
    const float* xb = x + (size_t)b * (NATOMS * 3);
    float* ob = out + (size_t)b * NN;

    const int tx = threadIdx.x & 31;   // j lane
    const int ty = threadIdx.x >> 5;   // warp id (0..7)

    // Stage the 33 i-points and 33 j-points.
    {
        int t = threadIdx.x;
        if (t < 66) {
            int local = (t < 33) ? t : t - 33;
            int base  = (t < 33) ? i0 : j0;
            int c = min(base + local, NATOMS - 1);
            float4 v = make_float4(xb[3 * c], xb[3 * c + 1], xb[3 * c + 2], 0.f);
            if (t < 33) si[local] = v; else sj4[local] = v;
        }
    }
    // Band-zero duty for diagonal tiles (cells disjoint from all compute writes).
    if (ty == 1 && ti == tj) {
        int r = i0 + tx;
        ob[r * 513] = 0.f;
        if (r < NATOMS - 1) { ob[r * 513 + 1] = 0.f; ob[r * 513 + 512] = 0.f; }
        if (ti == 0 && tx == 0) { ob[NATOMS - 1] = 0.f; ob[(NATOMS - 1) * NATOMS] = 0.f; }
    }
    __syncthreads();

    const int j = j0 + tx;
    const float4 P2 = sj4[tx];
    const float4 P3 = sj4[tx + 1];

    #pragma unroll 4
    for (int kk = 0; kk < 4; kk++) {
        const int ii = ty + 8 * kk;
        const int i  = i0 + ii;
        const float4 P0 = si[ii];
        const float4 P1 = si[ii + 1];

        F3 e0 = f3sub(P2, P0);
        F3 e1 = f3sub(P3, P0);
        F3 e2 = f3sub(P2, P1);
        F3 e3 = f3sub(P3, P1);

        F3 u0 = f3cross(e0, e1);
        F3 u1 = f3cross(e1, e3);
        F3 u2 = f3cross(e3, e2);
        F3 u3 = f3cross(e2, e0);

        float r0 = rsqrt_a(f3dot(u0, u0));
        float r1 = rsqrt_a(f3dot(u1, u1));
        float r2 = rsqrt_a(f3dot(u2, u2));
        float r3 = rsqrt_a(f3dot(u3, u3));

        float t01 = f3dot(u0, u1) * (r0 * r1);
        float t12 = f3dot(u1, u2) * (r1 * r2);
        float t23 = f3dot(u2, u3) * (r2 * r3);
        float t30 = f3dot(u3, u0) * (r3 * r0);

        float omega = asin_fast(t01) + asin_fast(t12) + asin_fast(t23) + asin_fast(t30);

        // sign(((p3-p2)x(p1-p0)).(p2-p0)) == sign(-(u0.e2))  [triple product]
        float sv  = -f3dot(u0, e2);
        float sgn = (sv > 0.f) ? 1.f : ((sv < 0.f) ? -1.f : 0.f);
        float wr  = omega * sgn * INV2PI;

        smwr[ii][tx] = wr;

        bool valid = (j >= i + 2) && (i <= NATOMS - 3) && (j <= NATOMS - 2);
        if (valid) {
            ob[(i + 1) * NATOMS + (j + 1)] = wr;               // upper, coalesced
            if (i == 0) {                                      // i==0 first-scatter survivors
                ob[j] = wr;                                    // (0, j) coalesced
                ob[j * NATOMS] = wr;                           // (j, 0) scattered, rare
            }
        }
    }
    __syncthreads();

    // Mirror phase: coalesced out[j+1][i+1] via transposed smem reads (stride 33 = conflict-free).
    #pragma unroll 4
    for (int kk = 0; kk < 4; kk++) {
        const int jj = ty + 8 * kk;
        const int jm = j0 + jj;
        const int im = i0 + tx;
        float v = smwr[tx][jj];
        bool valid = (jm >= im + 2) && (im <= NATOMS - 3) && (jm <= NATOMS - 2);
        if (valid)
            ob[(jm + 1) * NATOMS + (im + 1)] = v;
    }
}

extern "C" void kernel_launch(void* const* d_in, const int* in_sizes, int n_in,
                              void* d_out, int out_size)
{
    int xi = (in_sizes[0] == BATCH * NATOMS * 3) ? 0 : 1;
    const float* x   = (const float*)d_in[xi];
    float*       out = (float*)d_out;

    dim3 grid(NTILES, BATCH);
    writhe_tile_kernel<<<grid, 256>>>(x, out);
}

// round 4
// speedup vs baseline: 2.0228x; 1.1293x over previous
#include <cuda_runtime.h>

#define NATOMS 512
#define BATCH  32
#define NN     (NATOMS * NATOMS)
#define INV2PI 0.15915494309189535f
#define NT     16                       // 512/32 tiles per axis
#define NTILES (NT * (NT + 1) / 2)      // 136

struct F3 { float x, y, z; };

__device__ __forceinline__ F3 f3sub(float4 a, float4 b) { return {a.x - b.x, a.y - b.y, a.z - b.z}; }
__device__ __forceinline__ F3 f3cross(F3 a, F3 b) {
    return {a.y * b.z - a.z * b.y,
            a.z * b.x - a.x * b.z,
            a.x * b.y - a.y * b.x};
}
__device__ __forceinline__ float f3dot(F3 a, F3 b) { return a.x * b.x + a.y * b.y + a.z * b.z; }

__device__ __forceinline__ float rsqrt_a(float x) {
    float r; asm("rsqrt.approx.f32 %0, %1;" : "=f"(r) : "f"(x)); return r;
}
__device__ __forceinline__ float sqrt_a(float x) {
    float r; asm("sqrt.approx.f32 %0, %1;" : "=f"(r) : "f"(x)); return r;
}

// ---- packed f32x2 helpers (non-volatile: CSE-able) ----
__device__ __forceinline__ unsigned long long pk2(float lo, float hi) {
    unsigned long long r;
    asm("mov.b64 %0, {%1, %2};" : "=l"(r) : "f"(lo), "f"(hi));
    return r;
}
__device__ __forceinline__ void upk2(unsigned long long v, float& lo, float& hi) {
    asm("mov.b64 {%0, %1}, %2;" : "=f"(lo), "=f"(hi) : "l"(v));
}
__device__ __forceinline__ unsigned long long fma2(unsigned long long a,
                                                   unsigned long long b,
                                                   unsigned long long c) {
    unsigned long long d;
    asm("fma.rn.f32x2 %0, %1, %2, %3;" : "=l"(d) : "l"(a), "l"(b), "l"(c));
    return d;
}

// Paired asin via A&S 4.4.46 (|err|<=2e-8): asin(t) = pi/2 - sqrt(1-t)*P7(t).
// Polynomial evaluated 2-wide with fma.rn.f32x2.
__device__ __forceinline__ void asin2_fast(float xa, float xb, float& ra, float& rb) {
    float ta = fminf(fabsf(xa), 1.0f);
    float tb = fminf(fabsf(xb), 1.0f);
    float sa = 1.0f - ta;
    float sb = 1.0f - tb;

    unsigned long long t2 = pk2(ta, tb);
    unsigned long long p  = pk2(-0.0012624911f, -0.0012624911f);
    p = fma2(p, t2, pk2( 0.0066700901f,  0.0066700901f));
    p = fma2(p, t2, pk2(-0.0170881256f, -0.0170881256f));
    p = fma2(p, t2, pk2( 0.0308918810f,  0.0308918810f));
    p = fma2(p, t2, pk2(-0.0501743046f, -0.0501743046f));
    p = fma2(p, t2, pk2( 0.0889789874f,  0.0889789874f));
    p = fma2(p, t2, pk2(-0.2145988016f, -0.2145988016f));
    p = fma2(p, t2, pk2( 1.5707963050f,  1.5707963050f));

    float pa, pb;
    upk2(p, pa, pb);
    float qa = fmaf(sqrt_a(sa), -pa, 1.5707963267948966f);
    float qb = fmaf(sqrt_a(sb), -pb, 1.5707963267948966f);
    ra = copysignf(qa, xa);
    rb = copysignf(qb, xb);
}

// One cell of the writhe sum. For !FIRST, (e0,e1,u0,r0) are taken from the
// carried state of cell (i-1, j): e0 = prev e2, e1 = prev e3, u0 = -prev u2
// (sign folded into t01/t30/sv via asin oddness), r0 = prev r2.
template<bool FIRST>
__device__ __forceinline__ float cell_wr(
    float4 P0, float4 P1, float4 P2, float4 P3,
    F3& ce2, F3& ce3, F3& cu2, float& cr2)
{
    F3 e0, e1, u0;
    float r0;
    if (FIRST) {
        e0 = f3sub(P2, P0);
        e1 = f3sub(P3, P0);
    } else {
        e0 = ce2;
        e1 = ce3;
    }
    F3 e2 = f3sub(P2, P1);
    F3 e3 = f3sub(P3, P1);

    if (FIRST) {
        u0 = f3cross(e0, e1);
        r0 = rsqrt_a(f3dot(u0, u0));
    } else {
        u0 = cu2;          // == -(true u0)
        r0 = cr2;
    }

    F3 u1 = f3cross(e1, e3);
    F3 u2 = f3cross(e3, e2);
    F3 u3 = f3cross(e2, e0);

    float r1 = rsqrt_a(f3dot(u1, u1));
    float r2 = rsqrt_a(f3dot(u2, u2));
    float r3 = rsqrt_a(f3dot(u3, u3));

    float d01 = f3dot(u0, u1);
    float d12 = f3dot(u1, u2);
    float d23 = f3dot(u2, u3);
    float d30 = f3dot(u3, u0);

    float t01, t30, sv;
    if (FIRST) {
        t01 = d01 * (r0 * r1);
        t30 = d30 * (r3 * r0);
        sv  = -f3dot(u0, e2);
    } else {
        t01 = -(d01 * (r0 * r1));   // neg folds into FMUL operand
        t30 = -(d30 * (r3 * r0));
        sv  = f3dot(u0, e2);
    }
    float t12 = d12 * (r1 * r2);
    float t23 = d23 * (r2 * r3);

    float a01, a12, a23, a30;
    asin2_fast(t01, t12, a01, a12);
    asin2_fast(t23, t30, a23, a30);
    float omega = (a01 + a12) + (a23 + a30);

    float sgn = (sv > 0.f) ? 1.f : ((sv < 0.f) ? -1.f : 0.f);
    float wr = omega * sgn * INV2PI;

    ce2 = e2; ce3 = e3; cu2 = u2; cr2 = r2;
    return wr;
}

// Segment set is exactly {(i,j): 0<=i<=509, i+2<=j<=510}.
// Final scatter state: every (i,j) owns out[i+1][j+1] (+mirror); i==0 segments
// additionally keep out[0][j] (+mirror). Never-written cells: |r-c|<=1 band,
// (0,511) and (511,0) — zeroed by the diagonal tiles.
__global__ __launch_bounds__(256) void writhe_tile_kernel(
    const float* __restrict__ x,
    float*       __restrict__ out)
{
    __shared__ float4 si[33];
    __shared__ float4 sj4[33];
    __shared__ float  smwr[32][33];

    int k = blockIdx.x, ti = 0;
    while (k >= NT - ti) { k -= NT - ti; ti++; }
    const int tj = ti + k;
    const int i0 = ti * 32, j0 = tj * 32;

    const int b = blockIdx.y;
    const float* xb = x + (size_t)b * (NATOMS * 3);
    float* ob = out + (size_t)b * NN;

    const int tx = threadIdx.x & 31;   // j lane
    const int ty = threadIdx.x >> 5;   // warp id (0..7) -> 4 consecutive i values

    {
        int t = threadIdx.x;
        if (t < 66) {
            int local = (t < 33) ? t : t - 33;
            int base  = (t < 33) ? i0 : j0;
            int c = min(base + local, NATOMS - 1);
            float4 v = make_float4(xb[3 * c], xb[3 * c + 1], xb[3 * c + 2], 0.f);
            if (t < 33) si[local] = v; else sj4[local] = v;
        }
    }
    if (ty == 1 && ti == tj) {
        int r = i0 + tx;
        ob[r * 513] = 0.f;
        if (r < NATOMS - 1) { ob[r * 513 + 1] = 0.f; ob[r * 513 + 512] = 0.f; }
        if (ti == 0 && tx == 0) { ob[NATOMS - 1] = 0.f; ob[(NATOMS - 1) * NATOMS] = 0.f; }
    }
    __syncthreads();

    const int j = j0 + tx;
    const float4 P2 = sj4[tx];
    const float4 P3 = sj4[tx + 1];
    const int ibase = 4 * ty;          // this thread's first local i

    F3 ce2, ce3, cu2;
    float cr2;

    #pragma unroll
    for (int kk = 0; kk < 4; kk++) {
        const int ii = ibase + kk;
        const int i  = i0 + ii;
        const float4 P0 = si[ii];
        const float4 P1 = si[ii + 1];

        float wr = (kk == 0)
            ? cell_wr<true >(P0, P1, P2, P3, ce2, ce3, cu2, cr2)
            : cell_wr<false>(P0, P1, P2, P3, ce2, ce3, cu2, cr2);

        smwr[ii][tx] = wr;

        bool valid = (j >= i + 2) && (i <= NATOMS - 3) && (j <= NATOMS - 2);
        if (valid) {
            ob[(i + 1) * NATOMS + (j + 1)] = wr;     // upper, coalesced
            if (i == 0) {
                ob[j] = wr;                          // (0, j) coalesced
                ob[j * NATOMS] = wr;                 // (j, 0) scattered, rare
            }
        }
    }
    __syncthreads();

    // Mirror: coalesced out[j+1][i+1] via transposed smem reads (stride 33).
    #pragma unroll
    for (int kk = 0; kk < 4; kk++) {
        const int jj = ibase + kk;
        const int jm = j0 + jj;
        const int im = i0 + tx;
        float v = smwr[tx][jj];
        bool valid = (jm >= im + 2) && (im <= NATOMS - 3) && (jm <= NATOMS - 2);
        if (valid)
            ob[(jm + 1) * NATOMS + (im + 1)] = v;
    }
}

extern "C" void kernel_launch(void* const* d_in, const int* in_sizes, int n_in,
                              void* d_out, int out_size)
{
    int xi = (in_sizes[0] == BATCH * NATOMS * 3) ? 0 : 1;
    const float* x   = (const float*)d_in[xi];
    float*       out = (float*)d_out;

    dim3 grid(NTILES, BATCH);
    writhe_tile_kernel<<<grid, 256>>>(x, out);
}

// round 5
// speedup vs baseline: 2.0250x; 1.0011x over previous
#include <cuda_runtime.h>

#define NATOMS 512
#define BATCH  32
#define NN     (NATOMS * NATOMS)
#define INV2PI 0.15915494309189535f
#define NT     16

struct F3 { float x, y, z; };

__device__ __forceinline__ F3 f3sub(float4 a, float4 b) { return {a.x - b.x, a.y - b.y, a.z - b.z}; }
__device__ __forceinline__ F3 f3cross(F3 a, F3 b) {
    return {a.y * b.z - a.z * b.y,
            a.z * b.x - a.x * b.z,
            a.x * b.y - a.y * b.x};
}
__device__ __forceinline__ float f3dot(F3 a, F3 b) { return a.x * b.x + a.y * b.y + a.z * b.z; }

__device__ __forceinline__ float rsqrt_a(float x) {
    float r; asm("rsqrt.approx.f32 %0, %1;" : "=f"(r) : "f"(x)); return r;
}
__device__ __forceinline__ float sqrt_a(float x) {
    float r; asm("sqrt.approx.f32 %0, %1;" : "=f"(r) : "f"(x)); return r;
}

// ---- packed f32x2 helpers (non-volatile: CSE-able) ----
__device__ __forceinline__ unsigned long long pk2(float lo, float hi) {
    unsigned long long r;
    asm("mov.b64 %0, {%1, %2};" : "=l"(r) : "f"(lo), "f"(hi));
    return r;
}
__device__ __forceinline__ void upk2(unsigned long long v, float& lo, float& hi) {
    asm("mov.b64 {%0, %1}, %2;" : "=f"(lo), "=f"(hi) : "l"(v));
}
__device__ __forceinline__ unsigned long long fma2(unsigned long long a,
                                                   unsigned long long b,
                                                   unsigned long long c) {
    unsigned long long d;
    asm("fma.rn.f32x2 %0, %1, %2, %3;" : "=l"(d) : "l"(a), "l"(b), "l"(c));
    return d;
}

// Paired asin via A&S 4.4.46 (|err|<=2e-8): asin(t) = pi/2 - sqrt(1-t)*P7(t).
__device__ __forceinline__ void asin2_fast(float xa, float xb, float& ra, float& rb) {
    float ta = fminf(fabsf(xa), 1.0f);
    float tb = fminf(fabsf(xb), 1.0f);
    float sa = 1.0f - ta;
    float sb = 1.0f - tb;

    unsigned long long t2 = pk2(ta, tb);
    unsigned long long p  = pk2(-0.0012624911f, -0.0012624911f);
    p = fma2(p, t2, pk2( 0.0066700901f,  0.0066700901f));
    p = fma2(p, t2, pk2(-0.0170881256f, -0.0170881256f));
    p = fma2(p, t2, pk2( 0.0308918810f,  0.0308918810f));
    p = fma2(p, t2, pk2(-0.0501743046f, -0.0501743046f));
    p = fma2(p, t2, pk2( 0.0889789874f,  0.0889789874f));
    p = fma2(p, t2, pk2(-0.2145988016f, -0.2145988016f));
    p = fma2(p, t2, pk2( 1.5707963050f,  1.5707963050f));

    float pa, pb;
    upk2(p, pa, pb);
    float qa = fmaf(sqrt_a(sa), -pa, 1.5707963267948966f);
    float qb = fmaf(sqrt_a(sb), -pb, 1.5707963267948966f);
    ra = copysignf(qa, xa);
    rb = copysignf(qb, xb);
}

// One cell. For !FIRST, (e0,e1,u0,r0) come from cell (i-1, j):
// e0 = prev e2, e1 = prev e3, u0 = -prev u2 (sign folded via asin oddness), r0 = prev r2.
template<bool FIRST>
__device__ __forceinline__ float cell_wr(
    float4 P0, float4 P1, float4 P2, float4 P3,
    F3& ce2, F3& ce3, F3& cu2, float& cr2)
{
    F3 e0, e1, u0;
    float r0;
    if (FIRST) {
        e0 = f3sub(P2, P0);
        e1 = f3sub(P3, P0);
    } else {
        e0 = ce2;
        e1 = ce3;
    }
    F3 e2 = f3sub(P2, P1);
    F3 e3 = f3sub(P3, P1);

    if (FIRST) {
        u0 = f3cross(e0, e1);
        r0 = rsqrt_a(f3dot(u0, u0));
    } else {
        u0 = cu2;          // == -(true u0)
        r0 = cr2;
    }

    F3 u1 = f3cross(e1, e3);
    F3 u2 = f3cross(e3, e2);
    F3 u3 = f3cross(e2, e0);

    float r1 = rsqrt_a(f3dot(u1, u1));
    float r2 = rsqrt_a(f3dot(u2, u2));
    float r3 = rsqrt_a(f3dot(u3, u3));

    float d01 = f3dot(u0, u1);
    float d12 = f3dot(u1, u2);
    float d23 = f3dot(u2, u3);
    float d30 = f3dot(u3, u0);

    float t01, t30;
    if (FIRST) {
        t01 = d01 * (r0 * r1);
        t30 = d30 * (r3 * r0);
    } else {
        t01 = -(d01 * (r0 * r1));
        t30 = -(d30 * (r3 * r0));
    }
    float t12 = d12 * (r1 * r2);
    float t23 = d23 * (r2 * r3);

    float a01, a12, a23, a30;
    asin2_fast(t01, t12, a01, a12);
    asin2_fast(t23, t30, a23, a30);
    float om = ((a01 + a12) + (a23 + a30)) * INV2PI;

    // true sv = -(u0_true . e2); carried u0 is negated for !FIRST.
    float dsv = f3dot(u0, e2);
    unsigned smask;
    if (FIRST)
        smask = (__float_as_uint(dsv) ^ 0x80000000u) & 0x80000000u;
    else
        smask = __float_as_uint(dsv) & 0x80000000u;
    float wr = __uint_as_float(__float_as_uint(om) ^ smask);

    ce2 = e2; ce3 = e3; cu2 = u2; cr2 = r2;
    return wr;
}

// ---------- FAST kernel: tiles with 1<=ti, ti+2<=tj<=14. All cells valid. ----------
__global__ __launch_bounds__(256) void writhe_fast(
    const float* __restrict__ x,
    float*       __restrict__ out)
{
    __shared__ float4 si[33];
    __shared__ float4 sj4[33];
    __shared__ float  smwr[32][33];

    // decode k over {(ti,tj): 1<=ti, ti+2<=tj<=14}; row ti has 13-ti entries.
    int k = blockIdx.x, ti = 1;
    while (k >= 13 - ti) { k -= 13 - ti; ti++; }
    const int tj = ti + 2 + k;
    const int i0 = ti * 32, j0 = tj * 32;

    const int b = blockIdx.y;
    const float* xb = x + (size_t)b * (NATOMS * 3);
    float* ob = out + (size_t)b * NN;

    const int tx = threadIdx.x & 31;
    const int ty = threadIdx.x >> 5;

    {
        int t = threadIdx.x;
        if (t < 66) {
            int local = (t < 33) ? t : t - 33;
            int c = ((t < 33) ? i0 : j0) + local;
            float4 v = make_float4(xb[3 * c], xb[3 * c + 1], xb[3 * c + 2], 0.f);
            if (t < 33) si[local] = v; else sj4[local] = v;
        }
    }
    __syncthreads();

    const int j = j0 + tx;
    const float4 P2 = sj4[tx];
    const float4 P3 = sj4[tx + 1];
    const int ibase = 4 * ty;

    F3 ce2, ce3, cu2;
    float cr2;

    float* orow = ob + (size_t)(i0 + ibase + 1) * NATOMS + (j + 1);
    #pragma unroll
    for (int kk = 0; kk < 4; kk++) {
        const int ii = ibase + kk;
        const float4 P0 = si[ii];
        const float4 P1 = si[ii + 1];
        float wr = (kk == 0)
            ? cell_wr<true >(P0, P1, P2, P3, ce2, ce3, cu2, cr2)
            : cell_wr<false>(P0, P1, P2, P3, ce2, ce3, cu2, cr2);
        smwr[ii][tx] = wr;
        orow[kk * NATOMS] = wr;                       // coalesced, unconditional
    }
    __syncthreads();

    float* ocol = ob + (size_t)(j0 + ibase + 1) * NATOMS + (i0 + tx + 1);
    #pragma unroll
    for (int kk = 0; kk < 4; kk++) {
        ocol[kk * NATOMS] = smwr[tx][ibase + kk];     // coalesced, unconditional
    }
}

// ---------- GENERAL kernel: ti=0 row, diagonals, super-diagonals, tj=15 column ----------
__global__ __launch_bounds__(256) void writhe_general(
    const float* __restrict__ x,
    float*       __restrict__ out)
{
    __shared__ float4 si[33];
    __shared__ float4 sj4[33];
    __shared__ float  smwr[32][33];

    // closed-form decode of the 58 general tiles
    int bx = blockIdx.x, ti, tj;
    if (bx < 16)       { ti = 0;       tj = bx;      }
    else if (bx < 31)  { ti = bx - 15; tj = ti;      }   // diag 1..15
    else if (bx < 45)  { ti = bx - 30; tj = ti + 1;  }   // superdiag 1..14
    else               { ti = bx - 44; tj = 15;      }   // ti 1..13
    const int i0 = ti * 32, j0 = tj * 32;

    const int b = blockIdx.y;
    const float* xb = x + (size_t)b * (NATOMS * 3);
    float* ob = out + (size_t)b * NN;

    const int tx = threadIdx.x & 31;
    const int ty = threadIdx.x >> 5;

    {
        int t = threadIdx.x;
        if (t < 66) {
            int local = (t < 33) ? t : t - 33;
            int c = min(((t < 33) ? i0 : j0) + local, NATOMS - 1);
            float4 v = make_float4(xb[3 * c], xb[3 * c + 1], xb[3 * c + 2], 0.f);
            if (t < 33) si[local] = v; else sj4[local] = v;
        }
    }
    // Band-zero duty for diagonal tiles (cells never written by any scatter).
    if (ty == 1 && ti == tj) {
        int r = i0 + tx;
        ob[r * 513] = 0.f;
        if (r < NATOMS - 1) { ob[r * 513 + 1] = 0.f; ob[r * 513 + 512] = 0.f; }
        if (ti == 0 && tx == 0) { ob[NATOMS - 1] = 0.f; ob[(NATOMS - 1) * NATOMS] = 0.f; }
    }
    __syncthreads();

    const int j = j0 + tx;
    const float4 P2 = sj4[tx];
    const float4 P3 = sj4[tx + 1];
    const int ibase = 4 * ty;

    F3 ce2, ce3, cu2;
    float cr2;

    #pragma unroll
    for (int kk = 0; kk < 4; kk++) {
        const int ii = ibase + kk;
        const int i  = i0 + ii;
        const float4 P0 = si[ii];
        const float4 P1 = si[ii + 1];
        float wr = (kk == 0)
            ? cell_wr<true >(P0, P1, P2, P3, ce2, ce3, cu2, cr2)
            : cell_wr<false>(P0, P1, P2, P3, ce2, ce3, cu2, cr2);
        smwr[ii][tx] = wr;

        bool valid = (j >= i + 2) && (i <= NATOMS - 3) && (j <= NATOMS - 2);
        if (valid) {
            ob[(i + 1) * NATOMS + (j + 1)] = wr;
            if (i == 0) {
                ob[j] = wr;              // (0, j) first-scatter survivor
                ob[j * NATOMS] = wr;     // (j, 0)
            }
        }
    }
    __syncthreads();

    #pragma unroll
    for (int kk = 0; kk < 4; kk++) {
        const int jj = ibase + kk;
        const int jm = j0 + jj;
        const int im = i0 + tx;
        float v = smwr[tx][jj];
        bool valid = (jm >= im + 2) && (im <= NATOMS - 3) && (jm <= NATOMS - 2);
        if (valid)
            ob[(jm + 1) * NATOMS + (im + 1)] = v;
    }
}

extern "C" void kernel_launch(void* const* d_in, const int* in_sizes, int n_in,
                              void* d_out, int out_size)
{
    int xi = (in_sizes[0] == BATCH * NATOMS * 3) ? 0 : 1;
    const float* x   = (const float*)d_in[xi];
    float*       out = (float*)d_out;

    dim3 gf(78, BATCH);     // {1<=ti, ti+2<=tj<=14}
    dim3 gg(58, BATCH);     // ti=0 row, diag, superdiag, tj=15 column
    writhe_fast<<<gf, 256>>>(x, out);
    writhe_general<<<gg, 256>>>(x, out);
}

// round 6
// speedup vs baseline: 2.1972x; 1.0850x over previous
#include <cuda_runtime.h>

#define NATOMS 512
#define BATCH  32
#define NN     (NATOMS * NATOMS)
#define INV2PI 0.15915494309189535f
#define NT     16
#define NTILES (NT * (NT + 1) / 2)   // 136

struct F3 { float x, y, z; };

__device__ __forceinline__ F3 f3sub(float4 a, float4 b) { return {a.x - b.x, a.y - b.y, a.z - b.z}; }
__device__ __forceinline__ F3 f3cross(F3 a, F3 b) {
    return {a.y * b.z - a.z * b.y,
            a.z * b.x - a.x * b.z,
            a.x * b.y - a.y * b.x};
}
__device__ __forceinline__ float f3dot(F3 a, F3 b) { return a.x * b.x + a.y * b.y + a.z * b.z; }

__device__ __forceinline__ float rsqrt_a(float x) {
    float r; asm("rsqrt.approx.f32 %0, %1;" : "=f"(r) : "f"(x)); return r;
}
__device__ __forceinline__ float sqrt_a(float x) {
    float r; asm("sqrt.approx.f32 %0, %1;" : "=f"(r) : "f"(x)); return r;
}

// ---- packed f32x2 helpers (non-volatile: CSE-able) ----
__device__ __forceinline__ unsigned long long pk2(float lo, float hi) {
    unsigned long long r;
    asm("mov.b64 %0, {%1, %2};" : "=l"(r) : "f"(lo), "f"(hi));
    return r;
}
__device__ __forceinline__ void upk2(unsigned long long v, float& lo, float& hi) {
    asm("mov.b64 {%0, %1}, %2;" : "=f"(lo), "=f"(hi) : "l"(v));
}
__device__ __forceinline__ unsigned long long fma2(unsigned long long a,
                                                   unsigned long long b,
                                                   unsigned long long c) {
    unsigned long long d;
    asm("fma.rn.f32x2 %0, %1, %2, %3;" : "=l"(d) : "l"(a), "l"(b), "l"(c));
    return d;
}

// Paired asin via A&S 4.4.46 (|err|<=2e-8): asin(t) = pi/2 - sqrt(1-t)*P7(t).
__device__ __forceinline__ void asin2_fast(float xa, float xb, float& ra, float& rb) {
    float ta = fminf(fabsf(xa), 1.0f);
    float tb = fminf(fabsf(xb), 1.0f);
    float sa = 1.0f - ta;
    float sb = 1.0f - tb;

    unsigned long long t2 = pk2(ta, tb);
    unsigned long long p  = pk2(-0.0012624911f, -0.0012624911f);
    p = fma2(p, t2, pk2( 0.0066700901f,  0.0066700901f));
    p = fma2(p, t2, pk2(-0.0170881256f, -0.0170881256f));
    p = fma2(p, t2, pk2( 0.0308918810f,  0.0308918810f));
    p = fma2(p, t2, pk2(-0.0501743046f, -0.0501743046f));
    p = fma2(p, t2, pk2( 0.0889789874f,  0.0889789874f));
    p = fma2(p, t2, pk2(-0.2145988016f, -0.2145988016f));
    p = fma2(p, t2, pk2( 1.5707963050f,  1.5707963050f));

    float pa, pb;
    upk2(p, pa, pb);
    float qa = fmaf(sqrt_a(sa), -pa, 1.5707963267948966f);
    float qb = fmaf(sqrt_a(sb), -pb, 1.5707963267948966f);
    ra = copysignf(qa, xa);
    rb = copysignf(qb, xb);
}

// One cell using g = x[j+1]-x[j]:
//   e1 = e0+g, e3 = e2+g  =>  u0 = e0 x g,  u2 = g x e2,  u3 = e2 x e0,
//   u1 = e1 x e3 = u0 + u2 - u3   (cross replaced by adds; e3 never built).
// Carry from cell (i-1,j): e0 = prev e2; u0reg = prev u2 == -(true u0);
// r0 = prev r2. Negations fold into t01/t30 via asin oddness and into the
// sign mask.
template<bool FIRST>
__device__ __forceinline__ float cell_wr(
    float4 P0, float4 P1, F3 g, float4 P2,
    F3& ce2, F3& cu2, float& cr2)
{
    F3 e0;
    if (FIRST) e0 = f3sub(P2, P0);
    else       e0 = ce2;
    F3 e2 = f3sub(P2, P1);

    F3 u0; float r0;
    if (FIRST) {
        u0 = f3cross(e0, g);
        r0 = rsqrt_a(f3dot(u0, u0));
    } else {
        u0 = cu2;            // == -(true u0)
        r0 = cr2;
    }

    F3 u2 = f3cross(g, e2);
    F3 u3 = f3cross(e2, e0);

    F3 u1; // true u1 = u0_true + u2 - u3
    if (FIRST) u1 = { u0.x + u2.x - u3.x, u0.y + u2.y - u3.y, u0.z + u2.z - u3.z };
    else       u1 = { u2.x - u3.x - u0.x, u2.y - u3.y - u0.y, u2.z - u3.z - u0.z };

    float r1 = rsqrt_a(f3dot(u1, u1));
    float r2 = rsqrt_a(f3dot(u2, u2));
    float r3 = rsqrt_a(f3dot(u3, u3));

    float d01 = f3dot(u0, u1);
    float d12 = f3dot(u1, u2);
    float d23 = f3dot(u2, u3);
    float d30 = f3dot(u3, u0);

    float t01, t30;
    if (FIRST) {
        t01 = d01 * (r0 * r1);
        t30 = d30 * (r3 * r0);
    } else {
        t01 = -(d01 * (r0 * r1));
        t30 = -(d30 * (r3 * r0));
    }
    float t12 = d12 * (r1 * r2);
    float t23 = d23 * (r2 * r3);

    float a01, a12, a23, a30;
    asin2_fast(t01, t12, a01, a12);
    asin2_fast(t23, t30, a23, a30);
    float om = ((a01 + a12) + (a23 + a30)) * INV2PI;

    // true sv = -(u0_true . e2); carried u0reg is already negated.
    float dsv = f3dot(u0, e2);
    unsigned smask;
    if (FIRST)
        smask = (__float_as_uint(dsv) ^ 0x80000000u) & 0x80000000u;
    else
        smask = __float_as_uint(dsv) & 0x80000000u;
    float wr = __uint_as_float(__float_as_uint(om) ^ smask);

    ce2 = e2; cu2 = u2; cr2 = r2;
    return wr;
}

// Segment set: {(i,j): 0<=i<=509, i+2<=j<=510}. Final scatter state:
// every (i,j) owns out[i+1][j+1] (+mirror); i==0 also keeps out[0][j] (+mirror).
// Never-written cells (|r-c|<=1 band, (0,511),(511,0)) are zeroed by diagonal tiles.
__global__ __launch_bounds__(256) void writhe_tile_kernel(
    const float* __restrict__ x,
    float*       __restrict__ out)
{
    __shared__ float4 si[33];
    __shared__ float4 sj4[33];
    __shared__ float  smwr[32][33];

    int k = blockIdx.x, ti = 0;
    while (k >= NT - ti) { k -= NT - ti; ti++; }
    const int tj = ti + k;
    const int i0 = ti * 32, j0 = tj * 32;
    // All 1024 cells of this tile valid <=> ti>=1 (no i==0 specials),
    // tj>=ti+2 (j-i >= 33 everywhere), tj<=14 (j<=510 everywhere).
    const bool fastTile = (ti >= 1) && (tj >= ti + 2) && (tj <= 14);

    const int b = blockIdx.y;
    const float* xb = x + (size_t)b * (NATOMS * 3);
    float* ob = out + (size_t)b * NN;

    const int tx = threadIdx.x & 31;
    const int ty = threadIdx.x >> 5;

    {
        int t = threadIdx.x;
        if (t < 66) {
            int local = (t < 33) ? t : t - 33;
            int c = min(((t < 33) ? i0 : j0) + local, NATOMS - 1);
            float4 v = make_float4(xb[3 * c], xb[3 * c + 1], xb[3 * c + 2], 0.f);
            if (t < 33) si[local] = v; else sj4[local] = v;
        }
    }
    if (ty == 1 && ti == tj) {
        int r = i0 + tx;
        ob[r * 513] = 0.f;
        if (r < NATOMS - 1) { ob[r * 513 + 1] = 0.f; ob[r * 513 + 512] = 0.f; }
        if (ti == 0 && tx == 0) { ob[NATOMS - 1] = 0.f; ob[(NATOMS - 1) * NATOMS] = 0.f; }
    }
    __syncthreads();

    const int j = j0 + tx;
    const float4 P2 = sj4[tx];
    const float4 P3 = sj4[tx + 1];
    const F3 g = f3sub(P3, P2);          // x[j+1]-x[j], per-thread constant
    const int ibase = 4 * ty;

    F3 ce2, cu2;
    float cr2;
    float wrv[4];

    #pragma unroll
    for (int kk = 0; kk < 4; kk++) {
        const int ii = ibase + kk;
        const float4 P0 = si[ii];
        const float4 P1 = si[ii + 1];
        float wr = (kk == 0)
            ? cell_wr<true >(P0, P1, g, P2, ce2, cu2, cr2)
            : cell_wr<false>(P0, P1, g, P2, ce2, cu2, cr2);
        smwr[ii][tx] = wr;
        wrv[kk] = wr;
    }

    if (fastTile) {
        float* orow = ob + (size_t)(i0 + ibase + 1) * NATOMS + (j + 1);
        #pragma unroll
        for (int kk = 0; kk < 4; kk++)
            orow[kk * NATOMS] = wrv[kk];
    } else {
        #pragma unroll
        for (int kk = 0; kk < 4; kk++) {
            const int i = i0 + ibase + kk;
            bool valid = (j >= i + 2) && (i <= NATOMS - 3) && (j <= NATOMS - 2);
            if (valid) {
                ob[(i + 1) * NATOMS + (j + 1)] = wrv[kk];
                if (i == 0) {
                    ob[j] = wrv[kk];              // (0, j) first-scatter survivor
                    ob[j * NATOMS] = wrv[kk];     // (j, 0)
                }
            }
        }
    }
    __syncthreads();

    // Mirror: coalesced out[j+1][i+1] via transposed smem reads (stride 33).
    if (fastTile) {
        float* ocol = ob + (size_t)(j0 + ibase + 1) * NATOMS + (i0 + tx + 1);
        #pragma unroll
        for (int kk = 0; kk < 4; kk++)
            ocol[kk * NATOMS] = smwr[tx][ibase + kk];
    } else {
        #pragma unroll
        for (int kk = 0; kk < 4; kk++) {
            const int jj = ibase + kk;
            const int jm = j0 + jj;
            const int im = i0 + tx;
            float v = smwr[tx][jj];
            bool valid = (jm >= im + 2) && (im <= NATOMS - 3) && (jm <= NATOMS - 2);
            if (valid)
                ob[(jm + 1) * NATOMS + (im + 1)] = v;
        }
    }
}

extern "C" void kernel_launch(void* const* d_in, const int* in_sizes, int n_in,
                              void* d_out, int out_size)
{
    int xi = (in_sizes[0] == BATCH * NATOMS * 3) ? 0 : 1;
    const float* x   = (const float*)d_in[xi];
    float*       out = (float*)d_out;

    dim3 grid(NTILES, BATCH);
    writhe_tile_kernel<<<grid, 256>>>(x, out);
}